// round 1
// baseline (speedup 1.0000x reference)
#include <cuda_runtime.h>
#include <math.h>

#define V_N   50000
#define E_N   800000
#define DIM   64
#define NB    5
#define SCH   320   /* NB*DIM */
#define KTOT  384   /* DIM (K_self) + SCH (W_neigh) */

// Scratch: S[v, b*64+i] = sum over edges into v of basis_b * f_q_i  (64 MB, L2-resident)
__device__ float g_S[(size_t)V_N * SCH];

__global__ void zero_S_kernel() {
    size_t i = (size_t)blockIdx.x * blockDim.x + threadIdx.x;
    size_t n4 = (size_t)V_N * SCH / 4;
    if (i < n4) reinterpret_cast<float4*>(g_S)[i] = make_float4(0.f, 0.f, 0.f, 0.f);
}

// One half-warp (16 lanes) per edge: lane l owns channels [4l, 4l+4).
// Channels: 0..15 scalars (rho_0), 16..47 rho_1 pairs, 48..63 rho_2 pairs.
// All pairs are even-aligned so they live inside one float4.
__global__ __launch_bounds__(256) void edge_scatter_kernel(
    const float* __restrict__ x,
    const int*   __restrict__ ei,
    const float* __restrict__ angles,
    const float* __restrict__ trans)
{
    int tid  = blockIdx.x * blockDim.x + threadIdx.x;
    int warp = tid >> 5;
    int lane = tid & 31;
    int half = lane >> 4;
    int l    = lane & 15;
    int e    = warp * 2 + half;
    if (e >= E_N) return;

    int   src = ei[e];
    int   tgt = ei[E_N + e];
    float a   = angles[e];
    float t   = trans[e];

    const float4 xv = *reinterpret_cast<const float4*>(x + (size_t)src * DIM + 4 * l);
    float f0 = xv.x, f1 = xv.y, f2 = xv.z, f3 = xv.w;

    if (l >= 4) {  // rotate the two pairs by order*t
        float st, ct;
        sincosf(t, &st, &ct);
        if (l >= 12) {  // order 2: double angle
            float c2 = fmaf(2.f * ct, ct, -1.f);
            float s2 = 2.f * st * ct;
            ct = c2; st = s2;
        }
        float r0 = ct * f0 - st * f1;
        float r1 = st * f0 + ct * f1;
        float r2 = ct * f2 - st * f3;
        float r3 = st * f2 + ct * f3;
        f0 = r0; f1 = r1; f2 = r2; f3 = r3;
    }

    float sa, ca;
    sincosf(a, &sa, &ca);
    float c2a = fmaf(2.f * ca, ca, -1.f);
    float s2a = 2.f * sa * ca;
    float bas[NB] = {1.f, ca, sa, c2a, s2a};

    float* base = g_S + (size_t)tgt * SCH + 4 * l;
#pragma unroll
    for (int b = 0; b < NB; ++b) {
        float g0 = bas[b] * f0;
        float g1 = bas[b] * f1;
        float g2 = bas[b] * f2;
        float g3 = bas[b] * f3;
        asm volatile("red.global.add.v4.f32 [%0], {%1,%2,%3,%4};"
                     :: "l"(base + b * DIM), "f"(g0), "f"(g1), "f"(g2), "f"(g3)
                     : "memory");
    }
}

// One warp per vertex (grid-stride). Lane l owns output channels (2l, 2l+1),
// which also aligns with the irrep pair structure for the nonlinearity.
// out[v] = [x[v] | S[v]] @ Wc,  Wc[k][o] stacks K_self^T on top of W_neigh^T.
__global__ __launch_bounds__(256) void vertex_kernel(
    const float* __restrict__ x,
    const float* __restrict__ K_self,
    const float* __restrict__ Wn,
    const float* __restrict__ gamma,
    const float* __restrict__ beta,
    float* __restrict__ out)
{
    extern __shared__ float sh[];
    float* Wc    = sh;                 // [KTOT][64]
    float* stage = sh + KTOT * DIM;    // [warps][KTOT]

    int tid    = threadIdx.x;
    int lane   = tid & 31;
    int wid    = tid >> 5;
    int warps  = blockDim.x >> 5;

    // Stage combined weights transposed: Wc[k*64 + o]
    for (int idx = tid; idx < KTOT * DIM; idx += blockDim.x) {
        int k = idx >> 6;
        int o = idx & 63;
        float w;
        if (k < DIM) {
            w = K_self[o * DIM + k];                 // K_self[o][i], i=k
        } else {
            int kk = k - DIM;                        // kk = b*64 + i
            int b  = kk >> 6;
            int i  = kk & 63;
            w = Wn[b * DIM * DIM + o * DIM + i];     // W_neigh[b][o][i]
        }
        Wc[idx] = w;
    }
    __syncthreads();

    float ga0 = gamma[2 * lane],     ga1 = gamma[2 * lane + 1];
    float be0 = beta[2 * lane],      be1 = beta[2 * lane + 1];

    int nwarps = gridDim.x * warps;
    int gw     = blockIdx.x * warps + wid;
    float* st  = stage + wid * KTOT;

    for (int v = gw; v < V_N; v += nwarps) {
        const float* xr = x   + (size_t)v * DIM;
        const float* Sr = g_S + (size_t)v * SCH;

        st[lane]      = xr[lane];
        st[32 + lane] = xr[32 + lane];
#pragma unroll
        for (int j = 0; j < SCH / 32; ++j)
            st[DIM + j * 32 + lane] = Sr[j * 32 + lane];
        __syncwarp();

        float acc0 = 0.f, acc1 = 0.f;
#pragma unroll 8
        for (int k = 0; k < KTOT; ++k) {
            float  s = st[k];
            float2 w = *reinterpret_cast<const float2*>(&Wc[(k << 6) + 2 * lane]);
            acc0 = fmaf(s, w.x, acc0);
            acc1 = fmaf(s, w.y, acc1);
        }

        // LayerNorm over the 64 channels (biased variance)
        float sum = acc0 + acc1;
        float ssq = acc0 * acc0 + acc1 * acc1;
#pragma unroll
        for (int o = 16; o; o >>= 1) {
            sum += __shfl_xor_sync(0xffffffffu, sum, o);
            ssq += __shfl_xor_sync(0xffffffffu, ssq, o);
        }
        float mu  = sum * (1.f / 64.f);
        float var = ssq * (1.f / 64.f) - mu * mu;
        float rs  = rsqrtf(var + 1e-5f);
        float h0  = (acc0 - mu) * rs * ga0 + be0;
        float h1  = (acc1 - mu) * rs * ga1 + be1;

        // Nonlinearity: lanes 0..7 hold scalar channels (ReLU),
        // lanes 8..31 hold vector pairs (norm-gated softplus).
        if (lane < 8) {
            h0 = fmaxf(h0, 0.f);
            h1 = fmaxf(h1, 0.f);
        } else {
            float n  = sqrtf(h0 * h0 + h1 * h1);
            n        = fmaxf(n, 1e-8f);
            float sp = (n > 20.f) ? n : log1pf(expf(n));
            float sc = sp / n;
            h0 *= sc;
            h1 *= sc;
        }

        float2 o2;
        o2.x = h0 + st[2 * lane];
        o2.y = h1 + st[2 * lane + 1];
        __syncwarp();
        *reinterpret_cast<float2*>(out + (size_t)v * DIM + 2 * lane) = o2;
    }
}

extern "C" void kernel_launch(void* const* d_in, const int* in_sizes, int n_in,
                              void* d_out, int out_size)
{
    const float* x      = (const float*)d_in[0];
    const int*   ei     = (const int*)  d_in[1];
    const float* angles = (const float*)d_in[2];
    const float* trans  = (const float*)d_in[3];
    const float* K_self = (const float*)d_in[4];
    const float* Wn     = (const float*)d_in[5];
    const float* gamma  = (const float*)d_in[6];
    const float* beta   = (const float*)d_in[7];
    float* out = (float*)d_out;

    (void)in_sizes; (void)n_in; (void)out_size;

    // 1) Zero scratch S
    {
        size_t n4 = (size_t)V_N * SCH / 4;
        int blocks = (int)((n4 + 255) / 256);
        zero_S_kernel<<<blocks, 256>>>();
    }

    // 2) Edge scatter: 2 edges per warp, 8 warps per block
    {
        int blocks = (E_N / 2 + 7) / 8;   // 50000
        edge_scatter_kernel<<<blocks, 256>>>(x, ei, angles, trans);
    }

    // 3) Vertex contraction + LN + nonlin + residual
    {
        size_t shbytes = (size_t)(KTOT * DIM + 8 * KTOT) * sizeof(float);  // 110592 B
        cudaFuncSetAttribute(vertex_kernel,
                             cudaFuncAttributeMaxDynamicSharedMemorySize,
                             (int)shbytes);
        vertex_kernel<<<296, 256, shbytes>>>(x, K_self, Wn, gamma, beta, out);
    }
}